// round 4
// baseline (speedup 1.0000x reference)
#include <cuda_runtime.h>
#include <cuda_bf16.h>
#include <cstdint>
#include <cmath>

// ---------------- problem constants ----------------
#define Bc   4
#define Sc   2048
#define Dc   1024
#define Hh   16
#define DHh  64
#define FFc  4096
#define WINc 16
#define GMc  64
#define Rc   512
#define NWc  (Sc/WINc)     // 128
#define PAIRS (Sc/2)       // 1024
#define SKEEP (Sc-Rc)      // 1536
#define BS   (Bc*Sc)       // 8192

// ---------------- device scratch (static, no allocations) ----------------
__device__ float g_x2[(size_t)BS*Dc];    // residual stream (x2 -> x3 -> x4)
__device__ float g_h [(size_t)BS*Dc];    // normed activations
__device__ float g_q [(size_t)BS*Dc];
__device__ float g_k [(size_t)BS*Dc];
__device__ float g_v [(size_t)BS*Dc];
__device__ float g_o [(size_t)BS*Dc];
__device__ float g_f1[(size_t)BS*FFc];   // w1 branch -> gated
__device__ float g_sim [Bc*PAIRS];
__device__ int   g_flag[Bc*PAIRS];
__device__ int   g_pf  [Bc*PAIRS];       // exclusive prefix of flags

// ---------------- packed f32x2 helpers (Blackwell FFMA2 pipe, sm_100+) ----------------
__device__ __forceinline__ unsigned long long pk2(float lo, float hi) {
    unsigned long long r;
    asm("mov.b64 %0, {%1, %2};" : "=l"(r) : "f"(lo), "f"(hi));
    return r;
}
__device__ __forceinline__ unsigned long long dup2(float v) {
    unsigned long long r;
    asm("mov.b64 %0, {%1, %1};" : "=l"(r) : "f"(v));
    return r;
}
__device__ __forceinline__ void ffma2(unsigned long long &c,
                                      unsigned long long a,
                                      unsigned long long b) {
    asm("fma.rn.f32x2 %0, %1, %2, %0;" : "+l"(c) : "l"(a), "l"(b));
}
__device__ __forceinline__ void unpk2(unsigned long long p, float &lo, float &hi) {
    asm("mov.b64 {%0, %1}, %2;" : "=f"(lo), "=f"(hi) : "l"(p));
}

// ---------------- fused (optional span-embed) + RMSNorm ----------------
template<bool ADDSPAN>
__global__ __launch_bounds__(256) void rmsnorm_k(
    const float* __restrict__ xin, const int* __restrict__ span,
    const float* __restrict__ w_span, const float* __restrict__ w_norm,
    float* __restrict__ x2, float* __restrict__ h)
{
    int row = blockIdx.x;                  // b*S + s
    __shared__ float buf[Dc];
    __shared__ float red[256];
    float lg = 0.f;
    if (ADDSPAN) lg = log1pf((float)span[row]);
    float ss = 0.f;
    const float* xr = xin + (size_t)row*Dc;
    for (int d = threadIdx.x; d < Dc; d += 256) {
        float v = xr[d];
        if (ADDSPAN) v += lg * w_span[d];
        buf[d] = v;
        ss += v*v;
    }
    red[threadIdx.x] = ss; __syncthreads();
    for (int s = 128; s > 0; s >>= 1) {
        if (threadIdx.x < s) red[threadIdx.x] += red[threadIdx.x+s];
        __syncthreads();
    }
    float scale = rsqrtf(red[0]/(float)Dc + 1e-6f);
    for (int d = threadIdx.x; d < Dc; d += 256) {
        float v = buf[d];
        if (ADDSPAN) x2[(size_t)row*Dc + d] = v;
        h[(size_t)row*Dc + d] = v * scale * w_norm[d];
    }
}

// ---------------- double-buffered fp32 SGEMM on the FFMA2 pipe ----------------
// EPI: 0 -> C = A*B
//      1 -> C = AUX + A*B                 (residual)
//      2 -> C = silu(AUX) * (A*B)         (gated FFN, AUX==C allowed in-place)
template<int EPI>
__global__ __launch_bounds__(256) void sgemm_db(
    const float* __restrict__ A, const float* __restrict__ B,
    const float* __restrict__ AUX, float* __restrict__ C,
    int M, int N, int K)
{
    __shared__ float As[2][8][128];
    __shared__ float Bs[2][8][128];
    int tid = threadIdx.x;
    int bn0 = blockIdx.x * 128;
    int bm0 = blockIdx.y * 128;
    int tx = tid & 15, ty = tid >> 4;

    int aRow = tid >> 1,  aCol = (tid & 1) * 4;
    int bRow = tid >> 5,  bCol = (tid & 31) * 4;

    const float* Aptr = A + (size_t)(bm0 + aRow)*K + aCol;
    const float* Bptr = B + (size_t)bRow*N + bn0 + bCol;

    // preload tile 0
    float4 av = *(const float4*)(Aptr);
    float4 bv = *(const float4*)(Bptr);
    As[0][aCol+0][aRow] = av.x; As[0][aCol+1][aRow] = av.y;
    As[0][aCol+2][aRow] = av.z; As[0][aCol+3][aRow] = av.w;
    *(float4*)&Bs[0][bRow][bCol] = bv;
    __syncthreads();

    // acc pairs along n: acc2[m][q] = (c[m][2q], c[m][2q+1])
    unsigned long long acc2[8][4];
    #pragma unroll
    for (int m = 0; m < 8; m++)
        #pragma unroll
        for (int q = 0; q < 4; q++) acc2[m][q] = 0ULL;

    int buf = 0;
    for (int k0 = 8; k0 <= K; k0 += 8) {
        bool more = (k0 < K);
        if (more) {
            av = *(const float4*)(Aptr + k0);
            bv = *(const float4*)(Bptr + (size_t)k0*N);
        }
        #pragma unroll
        for (int kk = 0; kk < 8; kk++) {
            float4 a0 = *(const float4*)&As[buf][kk][ty*8];
            float4 a1 = *(const float4*)&As[buf][kk][ty*8+4];
            float4 b0 = *(const float4*)&Bs[buf][kk][tx*8];
            float4 b1 = *(const float4*)&Bs[buf][kk][tx*8+4];
            unsigned long long bp[4];
            bp[0] = pk2(b0.x, b0.y); bp[1] = pk2(b0.z, b0.w);
            bp[2] = pk2(b1.x, b1.y); bp[3] = pk2(b1.z, b1.w);
            unsigned long long ad[8];
            ad[0] = dup2(a0.x); ad[1] = dup2(a0.y);
            ad[2] = dup2(a0.z); ad[3] = dup2(a0.w);
            ad[4] = dup2(a1.x); ad[5] = dup2(a1.y);
            ad[6] = dup2(a1.z); ad[7] = dup2(a1.w);
            #pragma unroll
            for (int m = 0; m < 8; m++)
                #pragma unroll
                for (int q = 0; q < 4; q++)
                    ffma2(acc2[m][q], ad[m], bp[q]);
        }
        if (more) {
            buf ^= 1;
            As[buf][aCol+0][aRow] = av.x; As[buf][aCol+1][aRow] = av.y;
            As[buf][aCol+2][aRow] = av.z; As[buf][aCol+3][aRow] = av.w;
            *(float4*)&Bs[buf][bRow][bCol] = bv;
            __syncthreads();
        }
    }

    #pragma unroll
    for (int m = 0; m < 8; m++) {
        float acc[8];
        #pragma unroll
        for (int q = 0; q < 4; q++) unpk2(acc2[m][q], acc[2*q], acc[2*q+1]);
        int row = bm0 + ty*8 + m;
        float* cp = C + (size_t)row*N + bn0 + tx*8;
        const float* rp = (EPI != 0) ? (AUX + (size_t)row*N + bn0 + tx*8) : nullptr;
        #pragma unroll
        for (int n = 0; n < 8; n += 4) {
            float4 o;
            o.x = acc[n+0]; o.y = acc[n+1]; o.z = acc[n+2]; o.w = acc[n+3];
            if (EPI == 1) {
                float4 rv = *(const float4*)(rp + n);
                o.x += rv.x; o.y += rv.y; o.z += rv.z; o.w += rv.w;
            } else if (EPI == 2) {
                float4 rv = *(const float4*)(rp + n);
                o.x *= rv.x/(1.f+expf(-rv.x));
                o.y *= rv.y/(1.f+expf(-rv.y));
                o.z *= rv.z/(1.f+expf(-rv.z));
                o.w *= rv.w/(1.f+expf(-rv.w));
            }
            *(float4*)(cp + n) = o;
        }
    }
}

// ---------------- RoPE on q and k ----------------
__global__ void rope_kernel(float* __restrict__ q, float* __restrict__ k,
                            const int* __restrict__ pos_ids,
                            const float* __restrict__ freqs)
{
    int idx = blockIdx.x * blockDim.x + threadIdx.x;   // B*S*H*32
    if (idx >= Bc*Sc*Hh*32) return;
    int f  = idx & 31;
    int h  = (idx >> 5) & (Hh-1);
    int s  = (idx >> 9) & (Sc-1);
    int b  = idx >> 20;
    float pos = (float)pos_ids[b*Sc + s];
    float ang = pos * freqs[f];
    float sn, cs;
    sincosf(ang, &sn, &cs);
    size_t base = ((size_t)(b*Sc + s))*Dc + h*DHh + f;
    float t1 = q[base], t2 = q[base+32];
    q[base]    = t1*cs - t2*sn;
    q[base+32] = t1*sn + t2*cs;
    t1 = k[base]; t2 = k[base+32];
    k[base]    = t1*cs - t2*sn;
    k[base+32] = t1*sn + t2*cs;
}

// ---------------- windowed attention: one block per (b, window, head) ----------------
__global__ __launch_bounds__(256) void attn_kernel(
    const float* __restrict__ q, const float* __restrict__ k,
    const float* __restrict__ v, float* __restrict__ o)
{
    int bid = blockIdx.x;
    int h = bid & (Hh-1);
    int n = (bid / Hh) & (NWc-1);
    int b = bid / (Hh*NWc);
    int s0 = n * WINc;

    __shared__ float qs[WINc][DHh+1];
    __shared__ float ks[WINc][DHh+1];
    __shared__ float vs[WINc][DHh+1];
    __shared__ float ps[WINc][WINc+1];

    int tid = threadIdx.x;
    for (int t = 0; t < 4; t++) {
        int i = tid + t*256;
        int r = i >> 6, d = i & 63;
        size_t ga = ((size_t)(b*Sc + s0 + r))*Dc + h*DHh + d;
        qs[r][d] = q[ga];
        ks[r][d] = k[ga];
        vs[r][d] = v[ga];
    }
    __syncthreads();
    {
        int i = tid >> 4, j = tid & 15;
        float acc = 0.f;
        #pragma unroll
        for (int d = 0; d < DHh; d++) acc += qs[i][d]*ks[j][d];
        ps[i][j] = acc * 0.125f;
    }
    __syncthreads();
    if (tid < WINc) {
        int i = tid;
        float mx = ps[i][0];
        #pragma unroll
        for (int j = 1; j < WINc; j++) mx = fmaxf(mx, ps[i][j]);
        float sum = 0.f;
        float e[WINc];
        #pragma unroll
        for (int j = 0; j < WINc; j++) { e[j] = expf(ps[i][j]-mx); sum += e[j]; }
        float inv = 1.f/sum;
        #pragma unroll
        for (int j = 0; j < WINc; j++) ps[i][j] = e[j]*inv;
    }
    __syncthreads();
    for (int t = 0; t < 4; t++) {
        int i = tid + t*256;
        int r = i >> 6, d = i & 63;
        float acc = 0.f;
        #pragma unroll
        for (int j = 0; j < WINc; j++) acc += ps[r][j]*vs[j][d];
        o[((size_t)(b*Sc + s0 + r))*Dc + h*DHh + d] = acc;
    }
}

// ---------------- metric + cosine sim per token pair ----------------
__global__ __launch_bounds__(256) void pair_sim(
    const float* __restrict__ x, const float* __restrict__ src,
    const float* __restrict__ pad, const float* __restrict__ w_metric,
    float* __restrict__ sim)
{
    int bp = blockIdx.x;
    int b = bp >> 10, j = bp & 1023;
    int re = 2*j;
    __shared__ float xe[Dc], xo[Dc];
    __shared__ float met[2*GMc];
    __shared__ float red[256];
    int tid = threadIdx.x;
    const float* xre = x + ((size_t)(b*Sc + re))*Dc;
    const float* xro = xre + Dc;
    for (int d = tid; d < Dc; d += 256) { xe[d] = xre[d]; xo[d] = xro[d]; }
    float se = 0.f, so = 0.f;
    const float* s_e = src + ((size_t)(b*Sc + re))*Sc;
    const float* s_o = s_e + Sc;
    const float* pd  = pad + b*Sc;
    for (int d = tid; d < Sc; d += 256) { se += s_e[d]*pd[d]; so += s_o[d]*pd[d]; }
    __syncthreads();
    if (tid < 2*GMc) {
        int r = tid >> 6, g = tid & 63;
        const float* xr = r ? xo : xe;
        float acc = 0.f;
        for (int d = 0; d < Dc; d++) acc += xr[d]*w_metric[d*GMc + g];
        met[tid] = acc;
    }
    __syncthreads();
    red[tid] = se; __syncthreads();
    for (int s = 128; s > 0; s >>= 1) { if (tid < s) red[tid] += red[tid+s]; __syncthreads(); }
    float real_e = red[0]; __syncthreads();
    red[tid] = so; __syncthreads();
    for (int s = 128; s > 0; s >>= 1) { if (tid < s) red[tid] += red[tid+s]; __syncthreads(); }
    float real_o = red[0]; __syncthreads();
    if (tid == 0) {
        float ne = 0.f, no = 0.f, dp = 0.f;
        #pragma unroll
        for (int g = 0; g < GMc; g++) {
            float a = met[g], bb2 = met[GMc+g];
            ne += a*a; no += bb2*bb2; dp += a*bb2;
        }
        ne = sqrtf(ne) + 1e-6f;
        no = sqrtf(no) + 1e-6f;
        float s2 = dp/(ne*no);
        bool ok = (real_e > 0.f) && (real_o > 0.f);
        sim[b*PAIRS + j] = ok ? s2 : -10000.0f;
    }
}

// ---------------- exact top-k flags (jax.lax.top_k semantics) + prefix ----------------
__global__ __launch_bounds__(1024) void topk_kernel(
    const float* __restrict__ sim, int* __restrict__ flag, int* __restrict__ pf)
{
    int b = blockIdx.x;
    __shared__ float ss[PAIRS];
    __shared__ int   fl[PAIRS];
    int t = threadIdx.x;
    ss[t] = sim[b*PAIRS + t];
    __syncthreads();
    float mine = ss[t];
    int rank = 0;
    for (int j = 0; j < PAIRS; j++) {
        float v = ss[j];
        rank += (v > mine) || (v == mine && j < t);
    }
    int f = (rank < Rc) ? 1 : 0;
    flag[b*PAIRS + t] = f;
    fl[t] = f;
    __syncthreads();
    if (t == 0) {
        int run = 0;
        for (int m = 0; m < PAIRS; m++) { pf[b*PAIRS + m] = run; run += fl[m]; }
    }
}

// ---------------- merge + gather + emit all four outputs ----------------
__global__ __launch_bounds__(256) void emit_kernel(
    const float* __restrict__ x, const float* __restrict__ src,
    const int* __restrict__ pos_ids, const int* __restrict__ span,
    const int* __restrict__ flag, const int* __restrict__ pf,
    float* __restrict__ out)
{
    int bid = blockIdx.x;
    int b = bid >> 11;           // /S
    int i = bid & (Sc-1);
    int m = i >> 1;
    int f = flag[b*PAIRS + m];
    bool odd = (i & 1) != 0;
    if (odd && f) return;        // dropped
    int t = i - pf[b*PAIRS + m];

    const size_t OX  = 0;
    const size_t OS  = (size_t)Bc*SKEEP*Dc;
    const size_t OP  = OS + (size_t)Bc*SKEEP*Sc;
    const size_t OSP = OP + (size_t)Bc*SKEEP;

    float* ox  = out + OX + ((size_t)b*SKEEP + t)*Dc;
    float* osr = out + OS + ((size_t)b*SKEEP + t)*Sc;
    const float* xi = x   + ((size_t)(b*Sc + i))*Dc;
    const float* si = src + ((size_t)(b*Sc + i))*Sc;

    bool merge = (!odd) && f;
    if (merge) {
        float sev = (float)span[b*Sc + i];
        float sov = (float)span[b*Sc + i + 1];
        float tot = sev + sov;
        const float* xn = xi + Dc;
        for (int d = threadIdx.x; d < Dc; d += 256)
            ox[d] = (sev*xi[d] + sov*xn[d]) / tot;
        const float* sn2 = si + Sc;
        for (int d = threadIdx.x; d < Sc; d += 256)
            osr[d] = si[d] + sn2[d];
    } else {
        for (int d = threadIdx.x; d < Dc; d += 256) ox[d] = xi[d];
        for (int d = threadIdx.x; d < Sc; d += 256) osr[d] = si[d];
    }
    if (threadIdx.x == 0) {
        out[OP  + (size_t)b*SKEEP + t] = (float)pos_ids[b*Sc + i];
        int sp = span[b*Sc + i];
        if (merge) sp += span[b*Sc + i + 1];
        out[OSP + (size_t)b*SKEEP + t] = (float)sp;
    }
}

// ---------------- host launcher ----------------
extern "C" void kernel_launch(void* const* d_in, const int* in_sizes, int n_in,
                              void* d_out, int out_size)
{
    int ro = (n_in >= 19) ? 0 : -1;   // r present as scalar input?
    const float* x        = (const float*)d_in[0];
    const float* source   = (const float*)d_in[1];
    const int*   pos_ids  = (const int*)  d_in[2];
    const int*   span     = (const int*)  d_in[3];
    const float* freqs    = (const float*)d_in[5+ro];
    const float* pad      = (const float*)d_in[6+ro];
    const float* w_span   = (const float*)d_in[8+ro];
    const float* w_norm1  = (const float*)d_in[9+ro];
    const float* wq       = (const float*)d_in[10+ro];
    const float* wk       = (const float*)d_in[11+ro];
    const float* wv       = (const float*)d_in[12+ro];
    const float* wo       = (const float*)d_in[13+ro];
    const float* w_norm2  = (const float*)d_in[14+ro];
    const float* w1       = (const float*)d_in[15+ro];
    const float* w3       = (const float*)d_in[16+ro];
    const float* w2       = (const float*)d_in[17+ro];
    const float* w_metric = (const float*)d_in[18+ro];
    float* out = (float*)d_out;

    float *px2, *ph, *pq, *pk, *pv, *po, *pf1, *psim;
    int *pflag, *ppf;
    cudaGetSymbolAddress((void**)&px2,  g_x2);
    cudaGetSymbolAddress((void**)&ph,   g_h);
    cudaGetSymbolAddress((void**)&pq,   g_q);
    cudaGetSymbolAddress((void**)&pk,   g_k);
    cudaGetSymbolAddress((void**)&pv,   g_v);
    cudaGetSymbolAddress((void**)&po,   g_o);
    cudaGetSymbolAddress((void**)&pf1,  g_f1);
    cudaGetSymbolAddress((void**)&psim, g_sim);
    cudaGetSymbolAddress((void**)&pflag,g_flag);
    cudaGetSymbolAddress((void**)&ppf,  g_pf);

    // 1) x2 = x + span-embed ; h = rmsnorm1(x2)
    rmsnorm_k<true><<<BS, 256>>>(x, span, w_span, w_norm1, px2, ph);
    // 2) q,k,v projections
    dim3 gD(Dc/128, BS/128);
    sgemm_db<0><<<gD, 256>>>(ph, wq, nullptr, pq, BS, Dc, Dc);
    sgemm_db<0><<<gD, 256>>>(ph, wk, nullptr, pk, BS, Dc, Dc);
    sgemm_db<0><<<gD, 256>>>(ph, wv, nullptr, pv, BS, Dc, Dc);
    // 3) rope on q,k
    rope_kernel<<<(Bc*Sc*Hh*32)/256, 256>>>(pq, pk, pos_ids, freqs);
    // 4) windowed attention
    attn_kernel<<<Bc*NWc*Hh, 256>>>(pq, pk, pv, po);
    // 5) x3 = x2 + o @ wo  (in place into g_x2)
    sgemm_db<1><<<gD, 256>>>(po, wo, px2, px2, BS, Dc, Dc);
    // 6) h = rmsnorm2(x3)
    rmsnorm_k<false><<<BS, 256>>>(px2, nullptr, nullptr, w_norm2, nullptr, ph);
    // 7) FFN: f1 = h@w1 ; f1 = silu(f1) * (h@w3)  [gate fused in epilogue]
    dim3 gF(FFc/128, BS/128);
    sgemm_db<0><<<gF, 256>>>(ph, w1, nullptr, pf1, BS, FFc, Dc);
    sgemm_db<2><<<gF, 256>>>(ph, w3, pf1, pf1, BS, FFc, Dc);
    // 8) x4 = x3 + gated @ w2  (in place)
    sgemm_db<1><<<gD, 256>>>(pf1, w2, px2, px2, BS, Dc, FFc);
    // 9) metric + cosine sim per pair
    pair_sim<<<Bc*PAIRS, 256>>>(px2, source, pad, w_metric, psim);
    // 10) exact top-k flags + prefix
    topk_kernel<<<Bc, 1024>>>(psim, pflag, ppf);
    // 11) merge + gather + emit
    emit_kernel<<<Bc*Sc, 256>>>(px2, source, pos_ids, span, pflag, ppf, out);
    (void)in_sizes; (void)out_size;
}

// round 5
// speedup vs baseline: 1.2412x; 1.2412x over previous
#include <cuda_runtime.h>
#include <cuda_bf16.h>
#include <cstdint>
#include <cmath>

// ---------------- problem constants ----------------
#define Bc   4
#define Sc   2048
#define Dc   1024
#define Hh   16
#define DHh  64
#define FFc  4096
#define WINc 16
#define GMc  64
#define Rc   512
#define NWc  (Sc/WINc)     // 128
#define PAIRS (Sc/2)       // 1024
#define SKEEP (Sc-Rc)      // 1536
#define BS   (Bc*Sc)       // 8192

// ---------------- device scratch (static, no allocations) ----------------
__device__ float g_x2[(size_t)BS*Dc];    // residual stream (x2 -> x3 -> x4)
__device__ float g_h [(size_t)BS*Dc];    // normed activations
__device__ float g_q [(size_t)BS*Dc];
__device__ float g_k [(size_t)BS*Dc];
__device__ float g_v [(size_t)BS*Dc];
__device__ float g_o [(size_t)BS*Dc];
__device__ float g_f1[(size_t)BS*FFc];   // w1 branch -> gated
__device__ float g_sim [Bc*PAIRS];
__device__ int   g_flag[Bc*PAIRS];
__device__ int   g_pf  [Bc*PAIRS];       // exclusive prefix of flags

// ---------------- tf32 helpers ----------------
__device__ __forceinline__ uint32_t f2tf32(float f) {
    uint32_t r; asm("cvt.rna.tf32.f32 %0, %1;" : "=r"(r) : "f"(f)); return r;
}
__device__ __forceinline__ void mma8(float* c, const uint32_t* a, const uint32_t* b) {
    asm volatile(
        "mma.sync.aligned.m16n8k8.row.col.f32.tf32.tf32.f32 "
        "{%0,%1,%2,%3},{%4,%5,%6,%7},{%8,%9},{%0,%1,%2,%3};"
        : "+f"(c[0]), "+f"(c[1]), "+f"(c[2]), "+f"(c[3])
        : "r"(a[0]), "r"(a[1]), "r"(a[2]), "r"(a[3]), "r"(b[0]), "r"(b[1]));
}

// ---------------- fused (optional span-embed) + RMSNorm ----------------
template<bool ADDSPAN>
__global__ __launch_bounds__(256) void rmsnorm_k(
    const float* __restrict__ xin, const int* __restrict__ span,
    const float* __restrict__ w_span, const float* __restrict__ w_norm,
    float* __restrict__ x2, float* __restrict__ h)
{
    int row = blockIdx.x;                  // b*S + s
    __shared__ float buf[Dc];
    __shared__ float red[256];
    float lg = 0.f;
    if (ADDSPAN) lg = log1pf((float)span[row]);
    float ss = 0.f;
    const float* xr = xin + (size_t)row*Dc;
    for (int d = threadIdx.x; d < Dc; d += 256) {
        float v = xr[d];
        if (ADDSPAN) v += lg * w_span[d];
        buf[d] = v;
        ss += v*v;
    }
    red[threadIdx.x] = ss; __syncthreads();
    for (int s = 128; s > 0; s >>= 1) {
        if (threadIdx.x < s) red[threadIdx.x] += red[threadIdx.x+s];
        __syncthreads();
    }
    float scale = rsqrtf(red[0]/(float)Dc + 1e-6f);
    for (int d = threadIdx.x; d < Dc; d += 256) {
        float v = buf[d];
        if (ADDSPAN) x2[(size_t)row*Dc + d] = v;
        h[(size_t)row*Dc + d] = v * scale * w_norm[d];
    }
}

// ---------------- 3xTF32 tensor-core GEMM (fp32-accurate) ----------------
// EPI: 0 -> C = A*B
//      1 -> C = AUX + A*B                 (residual)
//      2 -> C = silu(AUX) * (A*B)         (gated FFN, AUX==C allowed in-place)
// Block 128x128, BK=8, 8 warps (2 along M x 4 along N), warp tile 64x32.
template<int EPI>
__global__ __launch_bounds__(256) void tgemm(
    const float* __restrict__ A, const float* __restrict__ B,
    const float* __restrict__ AUX, float* __restrict__ C,
    int M, int N, int K)
{
    __shared__ float As[2][8][136];   // [k][m], stride 136 -> conflict-free frag loads
    __shared__ float Bs[2][8][136];   // [k][n]
    int tid  = threadIdx.x;
    int wid  = tid >> 5;
    int lane = tid & 31;
    int bn0 = blockIdx.x * 128;
    int bm0 = blockIdx.y * 128;
    int wm = (wid & 1) * 64;          // warp m offset within block
    int wn = (wid >> 1) * 32;         // warp n offset within block
    int qr = lane >> 2;               // 0..7
    int qc = lane & 3;                // 0..3

    // global->smem loaders (same mapping as prior rounds)
    int aRow = tid >> 1,  aCol = (tid & 1) * 4;
    int bRow = tid >> 5,  bCol = (tid & 31) * 4;
    const float* Aptr = A + (size_t)(bm0 + aRow)*K + aCol;
    const float* Bptr = B + (size_t)bRow*N + bn0 + bCol;

    float4 av = *(const float4*)(Aptr);
    float4 bv = *(const float4*)(Bptr);
    As[0][aCol+0][aRow] = av.x; As[0][aCol+1][aRow] = av.y;
    As[0][aCol+2][aRow] = av.z; As[0][aCol+3][aRow] = av.w;
    *(float4*)&Bs[0][bRow][bCol] = bv;
    __syncthreads();

    float acc[4][4][4];               // [mt][nt][c0..c3]
    #pragma unroll
    for (int mt = 0; mt < 4; mt++)
        #pragma unroll
        for (int nt = 0; nt < 4; nt++)
            #pragma unroll
            for (int r = 0; r < 4; r++) acc[mt][nt][r] = 0.f;

    int buf = 0;
    for (int k0 = 8; k0 <= K; k0 += 8) {
        bool more = (k0 < K);
        if (more) {
            av = *(const float4*)(Aptr + k0);
            bv = *(const float4*)(Bptr + (size_t)k0*N);
        }
        // B fragments: b0=(k=qc, n), b1=(k=qc+4, n); split into hi/lo tf32
        uint32_t bh[4][2], bl[4][2];
        #pragma unroll
        for (int nt = 0; nt < 4; nt++) {
            int n = wn + nt*8 + qr;
            float b0f = Bs[buf][qc][n];
            float b1f = Bs[buf][qc+4][n];
            bh[nt][0] = f2tf32(b0f);
            bh[nt][1] = f2tf32(b1f);
            bl[nt][0] = f2tf32(b0f - __uint_as_float(bh[nt][0]));
            bl[nt][1] = f2tf32(b1f - __uint_as_float(bh[nt][1]));
        }
        #pragma unroll
        for (int mt = 0; mt < 4; mt++) {
            int m = wm + mt*16 + qr;
            float a0f = As[buf][qc  ][m];
            float a1f = As[buf][qc  ][m+8];
            float a2f = As[buf][qc+4][m];
            float a3f = As[buf][qc+4][m+8];
            uint32_t ah[4], al[4];
            ah[0] = f2tf32(a0f); ah[1] = f2tf32(a1f);
            ah[2] = f2tf32(a2f); ah[3] = f2tf32(a3f);
            al[0] = f2tf32(a0f - __uint_as_float(ah[0]));
            al[1] = f2tf32(a1f - __uint_as_float(ah[1]));
            al[2] = f2tf32(a2f - __uint_as_float(ah[2]));
            al[3] = f2tf32(a3f - __uint_as_float(ah[3]));
            #pragma unroll
            for (int nt = 0; nt < 4; nt++) {
                mma8(acc[mt][nt], ah, bh[nt]);   // hi*hi
                mma8(acc[mt][nt], ah, bl[nt]);   // hi*lo
                mma8(acc[mt][nt], al, bh[nt]);   // lo*hi
            }
        }
        if (more) {
            buf ^= 1;
            As[buf][aCol+0][aRow] = av.x; As[buf][aCol+1][aRow] = av.y;
            As[buf][aCol+2][aRow] = av.z; As[buf][aCol+3][aRow] = av.w;
            *(float4*)&Bs[buf][bRow][bCol] = bv;
            __syncthreads();
        }
    }

    // epilogue: c0=(row,col), c1=(row,col+1), c2=(row+8,col), c3=(row+8,col+1)
    #pragma unroll
    for (int mt = 0; mt < 4; mt++) {
        int row = bm0 + wm + mt*16 + qr;
        #pragma unroll
        for (int nt = 0; nt < 4; nt++) {
            int col = bn0 + wn + nt*8 + 2*qc;
            #pragma unroll
            for (int half = 0; half < 2; half++) {
                int r = row + half*8;
                float v0 = acc[mt][nt][2*half+0];
                float v1 = acc[mt][nt][2*half+1];
                float* cp = C + (size_t)r*N + col;
                if (EPI == 1) {
                    const float* rp = AUX + (size_t)r*N + col;
                    float2 rv = *(const float2*)rp;
                    v0 += rv.x; v1 += rv.y;
                } else if (EPI == 2) {
                    const float* rp = AUX + (size_t)r*N + col;
                    float2 rv = *(const float2*)rp;
                    v0 *= rv.x/(1.f+expf(-rv.x));
                    v1 *= rv.y/(1.f+expf(-rv.y));
                }
                float2 o; o.x = v0; o.y = v1;
                *(float2*)cp = o;
            }
        }
    }
}

// ---------------- RoPE on q and k ----------------
__global__ void rope_kernel(float* __restrict__ q, float* __restrict__ k,
                            const int* __restrict__ pos_ids,
                            const float* __restrict__ freqs)
{
    int idx = blockIdx.x * blockDim.x + threadIdx.x;   // B*S*H*32
    if (idx >= Bc*Sc*Hh*32) return;
    int f  = idx & 31;
    int h  = (idx >> 5) & (Hh-1);
    int s  = (idx >> 9) & (Sc-1);
    int b  = idx >> 20;
    float pos = (float)pos_ids[b*Sc + s];
    float ang = pos * freqs[f];
    float sn, cs;
    sincosf(ang, &sn, &cs);
    size_t base = ((size_t)(b*Sc + s))*Dc + h*DHh + f;
    float t1 = q[base], t2 = q[base+32];
    q[base]    = t1*cs - t2*sn;
    q[base+32] = t1*sn + t2*cs;
    t1 = k[base]; t2 = k[base+32];
    k[base]    = t1*cs - t2*sn;
    k[base+32] = t1*sn + t2*cs;
}

// ---------------- windowed attention: one block per (b, window, head) ----------------
__global__ __launch_bounds__(256) void attn_kernel(
    const float* __restrict__ q, const float* __restrict__ k,
    const float* __restrict__ v, float* __restrict__ o)
{
    int bid = blockIdx.x;
    int h = bid & (Hh-1);
    int n = (bid / Hh) & (NWc-1);
    int b = bid / (Hh*NWc);
    int s0 = n * WINc;

    __shared__ float qs[WINc][DHh+1];
    __shared__ float ks[WINc][DHh+1];
    __shared__ float vs[WINc][DHh+1];
    __shared__ float ps[WINc][WINc+1];

    int tid = threadIdx.x;
    for (int t = 0; t < 4; t++) {
        int i = tid + t*256;
        int r = i >> 6, d = i & 63;
        size_t ga = ((size_t)(b*Sc + s0 + r))*Dc + h*DHh + d;
        qs[r][d] = q[ga];
        ks[r][d] = k[ga];
        vs[r][d] = v[ga];
    }
    __syncthreads();
    {
        int i = tid >> 4, j = tid & 15;
        float acc = 0.f;
        #pragma unroll
        for (int d = 0; d < DHh; d++) acc += qs[i][d]*ks[j][d];
        ps[i][j] = acc * 0.125f;
    }
    __syncthreads();
    if (tid < WINc) {
        int i = tid;
        float mx = ps[i][0];
        #pragma unroll
        for (int j = 1; j < WINc; j++) mx = fmaxf(mx, ps[i][j]);
        float sum = 0.f;
        float e[WINc];
        #pragma unroll
        for (int j = 0; j < WINc; j++) { e[j] = expf(ps[i][j]-mx); sum += e[j]; }
        float inv = 1.f/sum;
        #pragma unroll
        for (int j = 0; j < WINc; j++) ps[i][j] = e[j]*inv;
    }
    __syncthreads();
    for (int t = 0; t < 4; t++) {
        int i = tid + t*256;
        int r = i >> 6, d = i & 63;
        float acc = 0.f;
        #pragma unroll
        for (int j = 0; j < WINc; j++) acc += ps[r][j]*vs[j][d];
        o[((size_t)(b*Sc + s0 + r))*Dc + h*DHh + d] = acc;
    }
}

// ---------------- metric + cosine sim per token pair ----------------
__global__ __launch_bounds__(256) void pair_sim(
    const float* __restrict__ x, const float* __restrict__ src,
    const float* __restrict__ pad, const float* __restrict__ w_metric,
    float* __restrict__ sim)
{
    int bp = blockIdx.x;
    int b = bp >> 10, j = bp & 1023;
    int re = 2*j;
    __shared__ float xe[Dc], xo[Dc];
    __shared__ float met[2*GMc];
    __shared__ float red[256];
    int tid = threadIdx.x;
    const float* xre = x + ((size_t)(b*Sc + re))*Dc;
    const float* xro = xre + Dc;
    for (int d = tid; d < Dc; d += 256) { xe[d] = xre[d]; xo[d] = xro[d]; }
    float se = 0.f, so = 0.f;
    const float* s_e = src + ((size_t)(b*Sc + re))*Sc;
    const float* s_o = s_e + Sc;
    const float* pd  = pad + b*Sc;
    for (int d = tid; d < Sc; d += 256) { se += s_e[d]*pd[d]; so += s_o[d]*pd[d]; }
    __syncthreads();
    if (tid < 2*GMc) {
        int r = tid >> 6, g = tid & 63;
        const float* xr = r ? xo : xe;
        float acc = 0.f;
        for (int d = 0; d < Dc; d++) acc += xr[d]*w_metric[d*GMc + g];
        met[tid] = acc;
    }
    __syncthreads();
    red[tid] = se; __syncthreads();
    for (int s = 128; s > 0; s >>= 1) { if (tid < s) red[tid] += red[tid+s]; __syncthreads(); }
    float real_e = red[0]; __syncthreads();
    red[tid] = so; __syncthreads();
    for (int s = 128; s > 0; s >>= 1) { if (tid < s) red[tid] += red[tid+s]; __syncthreads(); }
    float real_o = red[0]; __syncthreads();
    if (tid == 0) {
        float ne = 0.f, no = 0.f, dp = 0.f;
        #pragma unroll
        for (int g = 0; g < GMc; g++) {
            float a = met[g], bb2 = met[GMc+g];
            ne += a*a; no += bb2*bb2; dp += a*bb2;
        }
        ne = sqrtf(ne) + 1e-6f;
        no = sqrtf(no) + 1e-6f;
        float s2 = dp/(ne*no);
        bool ok = (real_e > 0.f) && (real_o > 0.f);
        sim[b*PAIRS + j] = ok ? s2 : -10000.0f;
    }
}

// ---------------- exact top-k flags (jax.lax.top_k semantics) + prefix ----------------
__global__ __launch_bounds__(1024) void topk_kernel(
    const float* __restrict__ sim, int* __restrict__ flag, int* __restrict__ pf)
{
    int b = blockIdx.x;
    __shared__ float ss[PAIRS];
    __shared__ int   fl[PAIRS];
    int t = threadIdx.x;
    ss[t] = sim[b*PAIRS + t];
    __syncthreads();
    float mine = ss[t];
    int rank = 0;
    for (int j = 0; j < PAIRS; j++) {
        float v = ss[j];
        rank += (v > mine) || (v == mine && j < t);
    }
    int f = (rank < Rc) ? 1 : 0;
    flag[b*PAIRS + t] = f;
    fl[t] = f;
    __syncthreads();
    if (t == 0) {
        int run = 0;
        for (int m = 0; m < PAIRS; m++) { pf[b*PAIRS + m] = run; run += fl[m]; }
    }
}

// ---------------- merge + gather + emit all four outputs ----------------
__global__ __launch_bounds__(256) void emit_kernel(
    const float* __restrict__ x, const float* __restrict__ src,
    const int* __restrict__ pos_ids, const int* __restrict__ span,
    const int* __restrict__ flag, const int* __restrict__ pf,
    float* __restrict__ out)
{
    int bid = blockIdx.x;
    int b = bid >> 11;           // /S
    int i = bid & (Sc-1);
    int m = i >> 1;
    int f = flag[b*PAIRS + m];
    bool odd = (i & 1) != 0;
    if (odd && f) return;        // dropped
    int t = i - pf[b*PAIRS + m];

    const size_t OX  = 0;
    const size_t OS  = (size_t)Bc*SKEEP*Dc;
    const size_t OP  = OS + (size_t)Bc*SKEEP*Sc;
    const size_t OSP = OP + (size_t)Bc*SKEEP;

    float* ox  = out + OX + ((size_t)b*SKEEP + t)*Dc;
    float* osr = out + OS + ((size_t)b*SKEEP + t)*Sc;
    const float* xi = x   + ((size_t)(b*Sc + i))*Dc;
    const float* si = src + ((size_t)(b*Sc + i))*Sc;

    bool merge = (!odd) && f;
    if (merge) {
        float sev = (float)span[b*Sc + i];
        float sov = (float)span[b*Sc + i + 1];
        float tot = sev + sov;
        const float* xn = xi + Dc;
        for (int d = threadIdx.x; d < Dc; d += 256)
            ox[d] = (sev*xi[d] + sov*xn[d]) / tot;
        const float* sn2 = si + Sc;
        for (int d = threadIdx.x; d < Sc; d += 256)
            osr[d] = si[d] + sn2[d];
    } else {
        for (int d = threadIdx.x; d < Dc; d += 256) ox[d] = xi[d];
        for (int d = threadIdx.x; d < Sc; d += 256) osr[d] = si[d];
    }
    if (threadIdx.x == 0) {
        out[OP  + (size_t)b*SKEEP + t] = (float)pos_ids[b*Sc + i];
        int sp = span[b*Sc + i];
        if (merge) sp += span[b*Sc + i + 1];
        out[OSP + (size_t)b*SKEEP + t] = (float)sp;
    }
}

// ---------------- host launcher ----------------
extern "C" void kernel_launch(void* const* d_in, const int* in_sizes, int n_in,
                              void* d_out, int out_size)
{
    int ro = (n_in >= 19) ? 0 : -1;   // r present as scalar input?
    const float* x        = (const float*)d_in[0];
    const float* source   = (const float*)d_in[1];
    const int*   pos_ids  = (const int*)  d_in[2];
    const int*   span     = (const int*)  d_in[3];
    const float* freqs    = (const float*)d_in[5+ro];
    const float* pad      = (const float*)d_in[6+ro];
    const float* w_span   = (const float*)d_in[8+ro];
    const float* w_norm1  = (const float*)d_in[9+ro];
    const float* wq       = (const float*)d_in[10+ro];
    const float* wk       = (const float*)d_in[11+ro];
    const float* wv       = (const float*)d_in[12+ro];
    const float* wo       = (const float*)d_in[13+ro];
    const float* w_norm2  = (const float*)d_in[14+ro];
    const float* w1       = (const float*)d_in[15+ro];
    const float* w3       = (const float*)d_in[16+ro];
    const float* w2       = (const float*)d_in[17+ro];
    const float* w_metric = (const float*)d_in[18+ro];
    float* out = (float*)d_out;

    float *px2, *ph, *pq, *pk, *pv, *po, *pf1, *psim;
    int *pflag, *ppf;
    cudaGetSymbolAddress((void**)&px2,  g_x2);
    cudaGetSymbolAddress((void**)&ph,   g_h);
    cudaGetSymbolAddress((void**)&pq,   g_q);
    cudaGetSymbolAddress((void**)&pk,   g_k);
    cudaGetSymbolAddress((void**)&pv,   g_v);
    cudaGetSymbolAddress((void**)&po,   g_o);
    cudaGetSymbolAddress((void**)&pf1,  g_f1);
    cudaGetSymbolAddress((void**)&psim, g_sim);
    cudaGetSymbolAddress((void**)&pflag,g_flag);
    cudaGetSymbolAddress((void**)&ppf,  g_pf);

    // 1) x2 = x + span-embed ; h = rmsnorm1(x2)
    rmsnorm_k<true><<<BS, 256>>>(x, span, w_span, w_norm1, px2, ph);
    // 2) q,k,v projections (3xTF32 tensor-core)
    dim3 gD(Dc/128, BS/128);
    tgemm<0><<<gD, 256>>>(ph, wq, nullptr, pq, BS, Dc, Dc);
    tgemm<0><<<gD, 256>>>(ph, wk, nullptr, pk, BS, Dc, Dc);
    tgemm<0><<<gD, 256>>>(ph, wv, nullptr, pv, BS, Dc, Dc);
    // 3) rope on q,k
    rope_kernel<<<(Bc*Sc*Hh*32)/256, 256>>>(pq, pk, pos_ids, freqs);
    // 4) windowed attention
    attn_kernel<<<Bc*NWc*Hh, 256>>>(pq, pk, pv, po);
    // 5) x3 = x2 + o @ wo  (in place into g_x2)
    tgemm<1><<<gD, 256>>>(po, wo, px2, px2, BS, Dc, Dc);
    // 6) h = rmsnorm2(x3)
    rmsnorm_k<false><<<BS, 256>>>(px2, nullptr, nullptr, w_norm2, nullptr, ph);
    // 7) FFN: f1 = h@w1 ; f1 = silu(f1) * (h@w3)  [gate fused in epilogue]
    dim3 gF(FFc/128, BS/128);
    tgemm<0><<<gF, 256>>>(ph, w1, nullptr, pf1, BS, FFc, Dc);
    tgemm<2><<<gF, 256>>>(ph, w3, pf1, pf1, BS, FFc, Dc);
    // 8) x4 = x3 + gated @ w2  (in place)
    tgemm<1><<<gD, 256>>>(pf1, w2, px2, px2, BS, Dc, FFc);
    // 9) metric + cosine sim per pair
    pair_sim<<<Bc*PAIRS, 256>>>(px2, source, pad, w_metric, psim);
    // 10) exact top-k flags + prefix
    topk_kernel<<<Bc, 1024>>>(psim, pflag, ppf);
    // 11) merge + gather + emit
    emit_kernel<<<Bc*Sc, 256>>>(px2, source, pos_ids, span, pflag, ppf, out);
    (void)in_sizes; (void)out_size;
}

// round 7
// speedup vs baseline: 1.3155x; 1.0599x over previous
#include <cuda_runtime.h>
#include <cuda_bf16.h>
#include <cstdint>
#include <cmath>

// ---------------- problem constants ----------------
#define Bc   4
#define Sc   2048
#define Dc   1024
#define Hh   16
#define DHh  64
#define FFc  4096
#define WINc 16
#define GMc  64
#define Rc   512
#define NWc  (Sc/WINc)     // 128
#define PAIRS (Sc/2)       // 1024
#define SKEEP (Sc-Rc)      // 1536
#define BS   (Bc*Sc)       // 8192

// ---------------- device scratch (static, no allocations) ----------------
__device__ float g_x2[(size_t)BS*Dc];    // residual stream (x2 -> x3 -> x4)
__device__ float g_h [(size_t)BS*Dc];    // normed activations
__device__ float g_q [(size_t)BS*Dc];
__device__ float g_k [(size_t)BS*Dc];
__device__ float g_v [(size_t)BS*Dc];
__device__ float g_o [(size_t)BS*Dc];
__device__ float g_f1[(size_t)BS*FFc];   // w1 branch -> gated
__device__ float g_sim [Bc*PAIRS];
__device__ int   g_flag[Bc*PAIRS];
__device__ int   g_pf  [Bc*PAIRS];       // exclusive prefix of flags

// ---------------- tf32 helpers ----------------
__device__ __forceinline__ uint32_t f2tf32(float f) {
    uint32_t r; asm("cvt.rna.tf32.f32 %0, %1;" : "=r"(r) : "f"(f)); return r;
}
__device__ __forceinline__ void split2(float f, uint32_t &hi, uint32_t &lo) {
    hi = f2tf32(f);
    lo = f2tf32(f - __uint_as_float(hi));
}
__device__ __forceinline__ void mma8(float* c, const uint32_t* a, const uint32_t* b) {
    asm volatile(
        "mma.sync.aligned.m16n8k8.row.col.f32.tf32.tf32.f32 "
        "{%0,%1,%2,%3},{%4,%5,%6,%7},{%8,%9},{%0,%1,%2,%3};"
        : "+f"(c[0]), "+f"(c[1]), "+f"(c[2]), "+f"(c[3])
        : "r"(a[0]), "r"(a[1]), "r"(a[2]), "r"(a[3]), "r"(b[0]), "r"(b[1]));
}

// ---------------- fused (optional span-embed) + RMSNorm ----------------
template<bool ADDSPAN>
__global__ __launch_bounds__(256) void rmsnorm_k(
    const float* __restrict__ xin, const int* __restrict__ span,
    const float* __restrict__ w_span, const float* __restrict__ w_norm,
    float* __restrict__ x2, float* __restrict__ h)
{
    int row = blockIdx.x;                  // b*S + s
    __shared__ float buf[Dc];
    __shared__ float red[256];
    float lg = 0.f;
    if (ADDSPAN) lg = log1pf((float)span[row]);
    float ss = 0.f;
    const float* xr = xin + (size_t)row*Dc;
    for (int d = threadIdx.x; d < Dc; d += 256) {
        float v = xr[d];
        if (ADDSPAN) v += lg * w_span[d];
        buf[d] = v;
        ss += v*v;
    }
    red[threadIdx.x] = ss; __syncthreads();
    for (int s = 128; s > 0; s >>= 1) {
        if (threadIdx.x < s) red[threadIdx.x] += red[threadIdx.x+s];
        __syncthreads();
    }
    float scale = rsqrtf(red[0]/(float)Dc + 1e-6f);
    for (int d = threadIdx.x; d < Dc; d += 256) {
        float v = buf[d];
        if (ADDSPAN) x2[(size_t)row*Dc + d] = v;
        h[(size_t)row*Dc + d] = v * scale * w_norm[d];
    }
}

// ---------------- 3xTF32 tensor-core GEMM, split-at-store ----------------
// EPI: 0 -> C = A*B
//      1 -> C = AUX + A*B                 (residual)
//      2 -> C = silu(AUX) * (A*B)         (gated FFN, AUX==C allowed in-place)
// Block 128x128, BK=8, 8 warps (2 along M x 4 along N), warp tile 64x32.
// tf32 hi/lo planes built once per tile at the gmem->smem stage.
template<int EPI>
__global__ __launch_bounds__(256) void tgemm(
    const float* __restrict__ A, const float* __restrict__ B,
    const float* __restrict__ AUX, float* __restrict__ C,
    int M, int N, int K)
{
    __shared__ uint32_t AsH[2][8][136];   // [k][m] tf32 hi
    __shared__ uint32_t AsL[2][8][136];   // [k][m] tf32 lo
    __shared__ uint32_t BsH[2][8][136];   // [k][n]
    __shared__ uint32_t BsL[2][8][136];
    int tid  = threadIdx.x;
    int wid  = tid >> 5;
    int lane = tid & 31;
    int bn0 = blockIdx.x * 128;
    int bm0 = blockIdx.y * 128;
    int wm = (wid & 1) * 64;          // warp m offset within block
    int wn = (wid >> 1) * 32;         // warp n offset within block
    int qr = lane >> 2;               // 0..7
    int qc = lane & 3;                // 0..3

    int aRow = tid >> 1,  aCol = (tid & 1) * 4;
    int bRow = tid >> 5,  bCol = (tid & 31) * 4;
    const float* Aptr = A + (size_t)(bm0 + aRow)*K + aCol;
    const float* Bptr = B + (size_t)bRow*N + bn0 + bCol;

    float4 av = *(const float4*)(Aptr);
    float4 bv = *(const float4*)(Bptr);
    {
        uint32_t h0,l0,h1,l1,h2,l2,h3,l3;
        split2(av.x,h0,l0); split2(av.y,h1,l1);
        split2(av.z,h2,l2); split2(av.w,h3,l3);
        AsH[0][aCol+0][aRow]=h0; AsL[0][aCol+0][aRow]=l0;
        AsH[0][aCol+1][aRow]=h1; AsL[0][aCol+1][aRow]=l1;
        AsH[0][aCol+2][aRow]=h2; AsL[0][aCol+2][aRow]=l2;
        AsH[0][aCol+3][aRow]=h3; AsL[0][aCol+3][aRow]=l3;
        split2(bv.x,h0,l0); split2(bv.y,h1,l1);
        split2(bv.z,h2,l2); split2(bv.w,h3,l3);
        uint4 bh; bh.x=h0; bh.y=h1; bh.z=h2; bh.w=h3;
        uint4 bl; bl.x=l0; bl.y=l1; bl.z=l2; bl.w=l3;
        *(uint4*)&BsH[0][bRow][bCol] = bh;
        *(uint4*)&BsL[0][bRow][bCol] = bl;
    }
    __syncthreads();

    float acc[4][4][4];               // [mt][nt][c0..c3]
    #pragma unroll
    for (int mt = 0; mt < 4; mt++)
        #pragma unroll
        for (int nt = 0; nt < 4; nt++)
            #pragma unroll
            for (int r = 0; r < 4; r++) acc[mt][nt][r] = 0.f;

    int buf = 0;
    for (int k0 = 8; k0 <= K; k0 += 8) {
        bool more = (k0 < K);
        if (more) {
            av = *(const float4*)(Aptr + k0);
            bv = *(const float4*)(Bptr + (size_t)k0*N);
        }
        // B fragments: b0=(k=qc, n), b1=(k=qc+4, n)
        uint32_t bh[4][2], bl[4][2];
        #pragma unroll
        for (int nt = 0; nt < 4; nt++) {
            int n = wn + nt*8 + qr;
            bh[nt][0] = BsH[buf][qc  ][n];
            bh[nt][1] = BsH[buf][qc+4][n];
            bl[nt][0] = BsL[buf][qc  ][n];
            bl[nt][1] = BsL[buf][qc+4][n];
        }
        #pragma unroll
        for (int mt = 0; mt < 4; mt++) {
            int m = wm + mt*16 + qr;
            uint32_t ah[4], al[4];
            ah[0] = AsH[buf][qc  ][m];
            ah[1] = AsH[buf][qc  ][m+8];
            ah[2] = AsH[buf][qc+4][m];
            ah[3] = AsH[buf][qc+4][m+8];
            al[0] = AsL[buf][qc  ][m];
            al[1] = AsL[buf][qc  ][m+8];
            al[2] = AsL[buf][qc+4][m];
            al[3] = AsL[buf][qc+4][m+8];
            #pragma unroll
            for (int nt = 0; nt < 4; nt++) {
                mma8(acc[mt][nt], ah, bh[nt]);   // hi*hi
                mma8(acc[mt][nt], ah, bl[nt]);   // hi*lo
                mma8(acc[mt][nt], al, bh[nt]);   // lo*hi
            }
        }
        if (more) {
            buf ^= 1;
            uint32_t h0,l0,h1,l1,h2,l2,h3,l3;
            split2(av.x,h0,l0); split2(av.y,h1,l1);
            split2(av.z,h2,l2); split2(av.w,h3,l3);
            AsH[buf][aCol+0][aRow]=h0; AsL[buf][aCol+0][aRow]=l0;
            AsH[buf][aCol+1][aRow]=h1; AsL[buf][aCol+1][aRow]=l1;
            AsH[buf][aCol+2][aRow]=h2; AsL[buf][aCol+2][aRow]=l2;
            AsH[buf][aCol+3][aRow]=h3; AsL[buf][aCol+3][aRow]=l3;
            split2(bv.x,h0,l0); split2(bv.y,h1,l1);
            split2(bv.z,h2,l2); split2(bv.w,h3,l3);
            uint4 bhv; bhv.x=h0; bhv.y=h1; bhv.z=h2; bhv.w=h3;
            uint4 blv; blv.x=l0; blv.y=l1; blv.z=l2; blv.w=l3;
            *(uint4*)&BsH[buf][bRow][bCol] = bhv;
            *(uint4*)&BsL[buf][bRow][bCol] = blv;
            __syncthreads();
        }
    }

    // epilogue: c0=(row,col), c1=(row,col+1), c2=(row+8,col), c3=(row+8,col+1)
    #pragma unroll
    for (int mt = 0; mt < 4; mt++) {
        int row = bm0 + wm + mt*16 + qr;
        #pragma unroll
        for (int nt = 0; nt < 4; nt++) {
            int col = bn0 + wn + nt*8 + 2*qc;
            #pragma unroll
            for (int half = 0; half < 2; half++) {
                int r = row + half*8;
                float v0 = acc[mt][nt][2*half+0];
                float v1 = acc[mt][nt][2*half+1];
                float* cp = C + (size_t)r*N + col;
                if (EPI == 1) {
                    const float* rp = AUX + (size_t)r*N + col;
                    float2 rv = *(const float2*)rp;
                    v0 += rv.x; v1 += rv.y;
                } else if (EPI == 2) {
                    const float* rp = AUX + (size_t)r*N + col;
                    float2 rv = *(const float2*)rp;
                    v0 *= rv.x/(1.f+expf(-rv.x));
                    v1 *= rv.y/(1.f+expf(-rv.y));
                }
                float2 o; o.x = v0; o.y = v1;
                *(float2*)cp = o;
            }
        }
    }
}

// ---------------- RoPE on q and k ----------------
__global__ void rope_kernel(float* __restrict__ q, float* __restrict__ k,
                            const int* __restrict__ pos_ids,
                            const float* __restrict__ freqs)
{
    int idx = blockIdx.x * blockDim.x + threadIdx.x;   // B*S*H*32
    if (idx >= Bc*Sc*Hh*32) return;
    int f  = idx & 31;
    int h  = (idx >> 5) & (Hh-1);
    int s  = (idx >> 9) & (Sc-1);
    int b  = idx >> 20;
    float pos = (float)pos_ids[b*Sc + s];
    float ang = pos * freqs[f];
    float sn, cs;
    sincosf(ang, &sn, &cs);
    size_t base = ((size_t)(b*Sc + s))*Dc + h*DHh + f;
    float t1 = q[base], t2 = q[base+32];
    q[base]    = t1*cs - t2*sn;
    q[base+32] = t1*sn + t2*cs;
    t1 = k[base]; t2 = k[base+32];
    k[base]    = t1*cs - t2*sn;
    k[base+32] = t1*sn + t2*cs;
}

// ---------------- windowed attention: one block per (b, window, head) ----------------
__global__ __launch_bounds__(256) void attn_kernel(
    const float* __restrict__ q, const float* __restrict__ k,
    const float* __restrict__ v, float* __restrict__ o)
{
    int bid = blockIdx.x;
    int h = bid & (Hh-1);
    int n = (bid / Hh) & (NWc-1);
    int b = bid / (Hh*NWc);
    int s0 = n * WINc;

    __shared__ float qs[WINc][DHh+1];
    __shared__ float ks[WINc][DHh+1];
    __shared__ float vs[WINc][DHh+1];
    __shared__ float ps[WINc][WINc+1];

    int tid = threadIdx.x;
    for (int t = 0; t < 4; t++) {
        int i = tid + t*256;
        int r = i >> 6, d = i & 63;
        size_t ga = ((size_t)(b*Sc + s0 + r))*Dc + h*DHh + d;
        qs[r][d] = q[ga];
        ks[r][d] = k[ga];
        vs[r][d] = v[ga];
    }
    __syncthreads();
    {
        int i = tid >> 4, j = tid & 15;
        float acc = 0.f;
        #pragma unroll
        for (int d = 0; d < DHh; d++) acc += qs[i][d]*ks[j][d];
        ps[i][j] = acc * 0.125f;
    }
    __syncthreads();
    if (tid < WINc) {
        int i = tid;
        float mx = ps[i][0];
        #pragma unroll
        for (int j = 1; j < WINc; j++) mx = fmaxf(mx, ps[i][j]);
        float sum = 0.f;
        float e[WINc];
        #pragma unroll
        for (int j = 0; j < WINc; j++) { e[j] = expf(ps[i][j]-mx); sum += e[j]; }
        float inv = 1.f/sum;
        #pragma unroll
        for (int j = 0; j < WINc; j++) ps[i][j] = e[j]*inv;
    }
    __syncthreads();
    for (int t = 0; t < 4; t++) {
        int i = tid + t*256;
        int r = i >> 6, d = i & 63;
        float acc = 0.f;
        #pragma unroll
        for (int j = 0; j < WINc; j++) acc += ps[r][j]*vs[j][d];
        o[((size_t)(b*Sc + s0 + r))*Dc + h*DHh + d] = acc;
    }
}

// ---------------- metric + cosine sim per token pair ----------------
__global__ __launch_bounds__(256) void pair_sim(
    const float* __restrict__ x, const float* __restrict__ src,
    const float* __restrict__ pad, const float* __restrict__ w_metric,
    float* __restrict__ sim)
{
    int bp = blockIdx.x;
    int b = bp >> 10, j = bp & 1023;
    int re = 2*j;
    __shared__ float xe[Dc], xo[Dc];
    __shared__ float met[2*GMc];
    __shared__ float red[256];
    int tid = threadIdx.x;
    const float* xre = x + ((size_t)(b*Sc + re))*Dc;
    const float* xro = xre + Dc;
    for (int d = tid; d < Dc; d += 256) { xe[d] = xre[d]; xo[d] = xro[d]; }
    float se = 0.f, so = 0.f;
    const float* s_e = src + ((size_t)(b*Sc + re))*Sc;
    const float* s_o = s_e + Sc;
    const float* pd  = pad + b*Sc;
    for (int d = tid; d < Sc; d += 256) { se += s_e[d]*pd[d]; so += s_o[d]*pd[d]; }
    __syncthreads();
    if (tid < 2*GMc) {
        int r = tid >> 6, g = tid & 63;
        const float* xr = r ? xo : xe;
        float acc = 0.f;
        for (int d = 0; d < Dc; d++) acc += xr[d]*w_metric[d*GMc + g];
        met[tid] = acc;
    }
    __syncthreads();
    red[tid] = se; __syncthreads();
    for (int s = 128; s > 0; s >>= 1) { if (tid < s) red[tid] += red[tid+s]; __syncthreads(); }
    float real_e = red[0]; __syncthreads();
    red[tid] = so; __syncthreads();
    for (int s = 128; s > 0; s >>= 1) { if (tid < s) red[tid] += red[tid+s]; __syncthreads(); }
    float real_o = red[0]; __syncthreads();
    if (tid == 0) {
        float ne = 0.f, no = 0.f, dp = 0.f;
        #pragma unroll
        for (int g = 0; g < GMc; g++) {
            float a = met[g], bb2 = met[GMc+g];
            ne += a*a; no += bb2*bb2; dp += a*bb2;
        }
        ne = sqrtf(ne) + 1e-6f;
        no = sqrtf(no) + 1e-6f;
        float s2 = dp/(ne*no);
        bool ok = (real_e > 0.f) && (real_o > 0.f);
        sim[b*PAIRS + j] = ok ? s2 : -10000.0f;
    }
}

// ---------------- exact top-k flags (jax.lax.top_k semantics) + prefix ----------------
__global__ __launch_bounds__(1024) void topk_kernel(
    const float* __restrict__ sim, int* __restrict__ flag, int* __restrict__ pf)
{
    int b = blockIdx.x;
    __shared__ float ss[PAIRS];
    __shared__ int   fl[PAIRS];
    int t = threadIdx.x;
    ss[t] = sim[b*PAIRS + t];
    __syncthreads();
    float mine = ss[t];
    int rank = 0;
    for (int j = 0; j < PAIRS; j++) {
        float v = ss[j];
        rank += (v > mine) || (v == mine && j < t);
    }
    int f = (rank < Rc) ? 1 : 0;
    flag[b*PAIRS + t] = f;
    fl[t] = f;
    __syncthreads();
    if (t == 0) {
        int run = 0;
        for (int m = 0; m < PAIRS; m++) { pf[b*PAIRS + m] = run; run += fl[m]; }
    }
}

// ---------------- merge + gather + emit all four outputs ----------------
__global__ __launch_bounds__(256) void emit_kernel(
    const float* __restrict__ x, const float* __restrict__ src,
    const int* __restrict__ pos_ids, const int* __restrict__ span,
    const int* __restrict__ flag, const int* __restrict__ pf,
    float* __restrict__ out)
{
    int bid = blockIdx.x;
    int b = bid >> 11;           // /S
    int i = bid & (Sc-1);
    int m = i >> 1;
    int f = flag[b*PAIRS + m];
    bool odd = (i & 1) != 0;
    if (odd && f) return;        // dropped
    int t = i - pf[b*PAIRS + m];

    const size_t OX  = 0;
    const size_t OS  = (size_t)Bc*SKEEP*Dc;
    const size_t OP  = OS + (size_t)Bc*SKEEP*Sc;
    const size_t OSP = OP + (size_t)Bc*SKEEP;

    float* ox  = out + OX + ((size_t)b*SKEEP + t)*Dc;
    float* osr = out + OS + ((size_t)b*SKEEP + t)*Sc;
    const float* xi = x   + ((size_t)(b*Sc + i))*Dc;
    const float* si = src + ((size_t)(b*Sc + i))*Sc;

    bool merge = (!odd) && f;
    if (merge) {
        float sev = (float)span[b*Sc + i];
        float sov = (float)span[b*Sc + i + 1];
        float tot = sev + sov;
        const float* xn = xi + Dc;
        for (int d = threadIdx.x; d < Dc; d += 256)
            ox[d] = (sev*xi[d] + sov*xn[d]) / tot;
        const float* sn2 = si + Sc;
        for (int d = threadIdx.x; d < Sc; d += 256)
            osr[d] = si[d] + sn2[d];
    } else {
        for (int d = threadIdx.x; d < Dc; d += 256) ox[d] = xi[d];
        for (int d = threadIdx.x; d < Sc; d += 256) osr[d] = si[d];
    }
    if (threadIdx.x == 0) {
        out[OP  + (size_t)b*SKEEP + t] = (float)pos_ids[b*Sc + i];
        int sp = span[b*Sc + i];
        if (merge) sp += span[b*Sc + i + 1];
        out[OSP + (size_t)b*SKEEP + t] = (float)sp;
    }
}

// ---------------- host launcher ----------------
extern "C" void kernel_launch(void* const* d_in, const int* in_sizes, int n_in,
                              void* d_out, int out_size)
{
    int ro = (n_in >= 19) ? 0 : -1;   // r present as scalar input?
    const float* x        = (const float*)d_in[0];
    const float* source   = (const float*)d_in[1];
    const int*   pos_ids  = (const int*)  d_in[2];
    const int*   span     = (const int*)  d_in[3];
    const float* freqs    = (const float*)d_in[5+ro];
    const float* pad      = (const float*)d_in[6+ro];
    const float* w_span   = (const float*)d_in[8+ro];
    const float* w_norm1  = (const float*)d_in[9+ro];
    const float* wq       = (const float*)d_in[10+ro];
    const float* wk       = (const float*)d_in[11+ro];
    const float* wv       = (const float*)d_in[12+ro];
    const float* wo       = (const float*)d_in[13+ro];
    const float* w_norm2  = (const float*)d_in[14+ro];
    const float* w1       = (const float*)d_in[15+ro];
    const float* w3       = (const float*)d_in[16+ro];
    const float* w2       = (const float*)d_in[17+ro];
    const float* w_metric = (const float*)d_in[18+ro];
    float* out = (float*)d_out;

    float *px2, *ph, *pq, *pk, *pv, *po, *pf1, *psim;
    int *pflag, *ppf;
    cudaGetSymbolAddress((void**)&px2,  g_x2);
    cudaGetSymbolAddress((void**)&ph,   g_h);
    cudaGetSymbolAddress((void**)&pq,   g_q);
    cudaGetSymbolAddress((void**)&pk,   g_k);
    cudaGetSymbolAddress((void**)&pv,   g_v);
    cudaGetSymbolAddress((void**)&po,   g_o);
    cudaGetSymbolAddress((void**)&pf1,  g_f1);
    cudaGetSymbolAddress((void**)&psim, g_sim);
    cudaGetSymbolAddress((void**)&pflag,g_flag);
    cudaGetSymbolAddress((void**)&ppf,  g_pf);

    // 1) x2 = x + span-embed ; h = rmsnorm1(x2)
    rmsnorm_k<true><<<BS, 256>>>(x, span, w_span, w_norm1, px2, ph);
    // 2) q,k,v projections (3xTF32 tensor-core)
    dim3 gD(Dc/128, BS/128);
    tgemm<0><<<gD, 256>>>(ph, wq, nullptr, pq, BS, Dc, Dc);
    tgemm<0><<<gD, 256>>>(ph, wk, nullptr, pk, BS, Dc, Dc);
    tgemm<0><<<gD, 256>>>(ph, wv, nullptr, pv, BS, Dc, Dc);
    // 3) rope on q,k
    rope_kernel<<<(Bc*Sc*Hh*32)/256, 256>>>(pq, pk, pos_ids, freqs);
    // 4) windowed attention
    attn_kernel<<<Bc*NWc*Hh, 256>>>(pq, pk, pv, po);
    // 5) x3 = x2 + o @ wo  (in place into g_x2)
    tgemm<1><<<gD, 256>>>(po, wo, px2, px2, BS, Dc, Dc);
    // 6) h = rmsnorm2(x3)
    rmsnorm_k<false><<<BS, 256>>>(px2, nullptr, nullptr, w_norm2, nullptr, ph);
    // 7) FFN: f1 = h@w1 ; f1 = silu(f1) * (h@w3)  [gate fused in epilogue]
    dim3 gF(FFc/128, BS/128);
    tgemm<0><<<gF, 256>>>(ph, w1, nullptr, pf1, BS, FFc, Dc);
    tgemm<2><<<gF, 256>>>(ph, w3, pf1, pf1, BS, FFc, Dc);
    // 8) x4 = x3 + gated @ w2  (in place)
    tgemm<1><<<gD, 256>>>(pf1, w2, px2, px2, BS, Dc, FFc);
    // 9) metric + cosine sim per pair
    pair_sim<<<Bc*PAIRS, 256>>>(px2, source, pad, w_metric, psim);
    // 10) exact top-k flags + prefix
    topk_kernel<<<Bc, 1024>>>(psim, pflag, ppf);
    // 11) merge + gather + emit
    emit_kernel<<<Bc*Sc, 256>>>(px2, source, pos_ids, span, pflag, ppf, out);
    (void)in_sizes; (void)out_size;
}